// round 5
// baseline (speedup 1.0000x reference)
#include <cuda_runtime.h>
#include <cstdint>

#define SIGINV 50.0f     // 1 / (2 * 0.1^2)
#define EPSs   1e-8f

// Separable RBF tables (fp32), tf32-rounded transposed features
__device__ float g_ex[4][64][4096];
__device__ float g_ey[4][64][4096];
__device__ float g_ft[4][256][4096];   // Ft[b][e][n] = rna_tf32(F[b][n][e])

// ---------------- helpers ----------------
__device__ __forceinline__ uint32_t smem_u32(const void* p) {
    uint32_t a;
    asm("{ .reg .u64 t; cvta.to.shared.u64 t, %1; cvt.u32.u64 %0, t; }"
        : "=r"(a) : "l"(p));
    return a;
}
__device__ __forceinline__ uint32_t f2tf32(float x) {
    uint32_t r;
    asm("cvt.rna.tf32.f32 %0, %1;" : "=r"(r) : "f"(x));
    return r;
}
__device__ __forceinline__ uint32_t lds32(uint32_t a) {
    uint32_t v;
    asm volatile("ld.shared.b32 %0, [%1];" : "=r"(v) : "r"(a));
    return v;
}

// ---------------- pre-kernels ----------------
__global__ void __launch_bounds__(256) table_kernel(const float* __restrict__ pos) {
    int b = blockIdx.x >> 6, gi = blockIdx.x & 63;
    float gc = (float)gi * (1.0f / 63.0f);
    int t = threadIdx.x;
    const float2* p2 = (const float2*)pos + (size_t)b * 4096;
#pragma unroll
    for (int j = 0; j < 16; j++) {
        int n = t + j * 256;
        float2 p = p2[n];
        float dx = gc - p.x, dy = gc - p.y;
        g_ex[b][gi][n] = __expf(-SIGINV * dx * dx);
        g_ey[b][gi][n] = __expf(-SIGINV * dy * dy);
    }
}

__global__ void __launch_bounds__(256) transpose_kernel(const float* __restrict__ feat) {
    __shared__ float tile[32][33];
    int b = blockIdx.z, n0 = blockIdx.x * 32, e0 = blockIdx.y * 32;
    int tx = threadIdx.x & 31, ty = threadIdx.x >> 5;
    const float* src = feat + ((size_t)b * 4096 + n0) * 256 + e0;
#pragma unroll
    for (int j = 0; j < 4; j++)
        tile[ty + j * 8][tx] = src[(size_t)(ty + j * 8) * 256 + tx];
    __syncthreads();
    float* dst = &g_ft[b][e0][n0];
#pragma unroll
    for (int j = 0; j < 4; j++)
        dst[(size_t)(ty + j * 8) * 4096 + tx] =
            __uint_as_float(f2tf32(tile[tx][ty + j * 8]));
}

// ---------------- main mma.sync tf32 kernel ----------------
// block = (b, mt): D[128p x 256e] = W[128 x 4096] * Ft^T, K chunks of 32.
// 512 threads = 16 warps, warp tile 32p x 64e (4m x 4n).
// smem/stage: ws[128][36] (18432 B) + fs[256][36] (36864 B), double-buffered.
#define WSB   18432
#define STAGE 55296
#define SMEMT (2 * STAGE)   // 110592

__global__ void __launch_bounds__(512, 1) mma_kernel(float* __restrict__ out) {
    extern __shared__ char smem[];
    uint32_t sb = smem_u32(smem);
    const int t = threadIdx.x, w = t >> 5, l = t & 31;
    const int blk = blockIdx.x, b = blk >> 5, mt = blk & 31;

    // --- staging maps ---
    const int sr = t >> 2, kseg = (t & 3) * 8;            // ws row / 8-wide k seg
    const float* exrow = &g_ex[b][mt * 2 + (sr >> 6)][0];
    const float* eyrow = &g_ey[b][sr & 63][0];
    const uint32_t wsAddr = sb + sr * 144 + kseg * 4;
    const float* ftrow = &g_ft[b][t >> 1][0] + (t & 1) * 16;
    const uint32_t fsAddr = sb + WSB + (t >> 1) * 144 + (t & 1) * 64;

    // --- mma fragment maps: wm in 0..3 (32p), wn in 0..3 (64e) ---
    const int wm = w & 3, wn = w >> 2, g = l >> 2, tig = l & 3;
    const uint32_t aBase = sb + (wm * 32 + g) * 144 + tig * 4;
    const uint32_t bBase = sb + WSB + (wn * 64 + g) * 144 + tig * 4;

    float acc[2][8][4];
#pragma unroll
    for (int i = 0; i < 2; i++)
#pragma unroll
        for (int j = 0; j < 8; j++)
#pragma unroll
            for (int q = 0; q < 4; q++) acc[i][j][q] = 0.0f;
    float psum = 0.0f;

#define STAGE_CHUNK(c, s)                                                     \
    do {                                                                      \
        const uint32_t so = (s) * STAGE;                                      \
        const int nc = (c) * 32;                                              \
        const float* fsrc = ftrow + nc;                                       \
        _Pragma("unroll")                                                     \
        for (int j = 0; j < 4; j++)                                           \
            asm volatile("cp.async.cg.shared.global [%0], [%1], 16;"          \
                         :: "r"(fsAddr + so + 16 * j), "l"(fsrc + 4 * j)      \
                         : "memory");                                         \
        asm volatile("cp.async.commit_group;" ::: "memory");                  \
        _Pragma("unroll")                                                     \
        for (int q = 0; q < 2; q++) {                                         \
            float4 ex = *(const float4*)(exrow + nc + kseg + 4 * q);          \
            float4 ey = *(const float4*)(eyrow + nc + kseg + 4 * q);          \
            float p0 = ex.x * ey.x, p1 = ex.y * ey.y;                         \
            float p2 = ex.z * ey.z, p3 = ex.w * ey.w;                         \
            psum += (p0 + p1) + (p2 + p3);                                    \
            uint32_t w0 = f2tf32(p0), w1 = f2tf32(p1);                        \
            uint32_t w2 = f2tf32(p2), w3 = f2tf32(p3);                        \
            asm volatile("st.shared.v4.b32 [%0], {%1,%2,%3,%4};"              \
                         :: "r"(wsAddr + so + 16 * q),                        \
                            "r"(w0), "r"(w1), "r"(w2), "r"(w3) : "memory");   \
        }                                                                     \
    } while (0)

    STAGE_CHUNK(0, 0);

    for (int c = 0; c < 128; c++) {
        const int s = c & 1;
        if (c < 127) {
            STAGE_CHUNK(c + 1, s ^ 1);
            asm volatile("cp.async.wait_group 1;" ::: "memory");
        } else {
            asm volatile("cp.async.wait_group 0;" ::: "memory");
        }
        __syncthreads();

        const uint32_t so = s * STAGE;
#pragma unroll
        for (int kt = 0; kt < 4; kt++) {
            uint32_t a[2][4];
#pragma unroll
            for (int i = 0; i < 2; i++) {
                uint32_t ad = aBase + so + i * 2304 + kt * 32;
                a[i][0] = lds32(ad);
                a[i][1] = lds32(ad + 1152);
                a[i][2] = lds32(ad + 16);
                a[i][3] = lds32(ad + 1152 + 16);
            }
#pragma unroll
            for (int jn = 0; jn < 8; jn++) {
                uint32_t bd = bBase + so + jn * 1152 + kt * 32;
                uint32_t b0 = lds32(bd), b1 = lds32(bd + 16);
#pragma unroll
                for (int i = 0; i < 2; i++) {
                    float* d = acc[i][jn];
                    asm volatile(
                        "mma.sync.aligned.m16n8k8.row.col.f32.tf32.tf32.f32 "
                        "{%0,%1,%2,%3}, {%4,%5,%6,%7}, {%8,%9}, {%0,%1,%2,%3};"
                        : "+f"(d[0]), "+f"(d[1]), "+f"(d[2]), "+f"(d[3])
                        : "r"(a[i][0]), "r"(a[i][1]), "r"(a[i][2]), "r"(a[i][3]),
                          "r"(b0), "r"(b1));
                }
            }
        }
        __syncthreads();
    }

    // --- exact fp32 row-sum reduction (replaces sum_kernel) ---
    float* sm = (float*)smem;          // stage buffers are dead now
    sm[t] = psum;
    __syncthreads();
    if (t < 128)
        sm[512 + t] = (sm[4 * t] + sm[4 * t + 1]) + (sm[4 * t + 2] + sm[4 * t + 3]);
    __syncthreads();

    // --- epilogue: normalize, scatter to [b][e][gx][gy] ---
    const size_t obase = (size_t)b * 256 * 4096;
#pragma unroll
    for (int i = 0; i < 2; i++) {
        int lp = wm * 32 + i * 16 + g;
        int p0 = mt * 128 + lp, p1 = p0 + 8;
        float inv0 = 1.0f / (sm[512 + lp] + EPSs);
        float inv1 = 1.0f / (sm[512 + lp + 8] + EPSs);
#pragma unroll
        for (int jn = 0; jn < 8; jn++) {
            int e0 = wn * 64 + jn * 8 + tig * 2;
            float* o0 = out + obase + (size_t)e0 * 4096;
            float* o1 = o0 + 4096;
            o0[p0] = acc[i][jn][0] * inv0;
            o1[p0] = acc[i][jn][1] * inv0;
            o0[p1] = acc[i][jn][2] * inv1;
            o1[p1] = acc[i][jn][3] * inv1;
        }
    }
}

extern "C" void kernel_launch(void* const* d_in, const int* in_sizes, int n_in,
                              void* d_out, int out_size) {
    const float* feat = (const float*)d_in[0];  // [4,4096,256]
    const float* pos  = (const float*)d_in[1];  // [4,4096,2]
    float* out = (float*)d_out;                 // [4,256,64,64]

    cudaFuncSetAttribute(mma_kernel,
                         cudaFuncAttributeMaxDynamicSharedMemorySize, SMEMT);

    table_kernel<<<256, 256>>>(pos);
    transpose_kernel<<<dim3(128, 8, 4), 256>>>(feat);
    mma_kernel<<<128, 512, SMEMT>>>(out);
}

// round 6
// speedup vs baseline: 1.4047x; 1.4047x over previous
#include <cuda_runtime.h>
#include <cstdint>

#define SIGINV 50.0f     // 1 / (2 * 0.1^2)
#define EPSs   1e-8f

// Separable RBF tables (fp32), tf32-rounded transposed features
__device__ float g_ex[4][64][4096];
__device__ float g_ey[4][64][4096];
__device__ float g_ft[4][256][4096];   // Ft[b][e][n] = rna_tf32(F[b][n][e])

// ---------------- helpers ----------------
__device__ __forceinline__ uint32_t smem_u32(const void* p) {
    uint32_t a;
    asm("{ .reg .u64 t; cvta.to.shared.u64 t, %1; cvt.u32.u64 %0, t; }"
        : "=r"(a) : "l"(p));
    return a;
}
__device__ __forceinline__ uint32_t f2tf32(float x) {
    uint32_t r;
    asm("cvt.rna.tf32.f32 %0, %1;" : "=r"(r) : "f"(x));
    return r;
}
__device__ __forceinline__ uint32_t lds32(uint32_t a) {
    uint32_t v;
    asm volatile("ld.shared.b32 %0, [%1];" : "=r"(v) : "r"(a));
    return v;
}

// ---------------- pre-kernels ----------------
__global__ void __launch_bounds__(256) table_kernel(const float* __restrict__ pos) {
    int b = blockIdx.x >> 6, gi = blockIdx.x & 63;
    float gc = (float)gi * (1.0f / 63.0f);
    int t = threadIdx.x;
    const float2* p2 = (const float2*)pos + (size_t)b * 4096;
#pragma unroll
    for (int j = 0; j < 16; j++) {
        int n = t + j * 256;
        float2 p = p2[n];
        float dx = gc - p.x, dy = gc - p.y;
        g_ex[b][gi][n] = __expf(-SIGINV * dx * dx);
        g_ey[b][gi][n] = __expf(-SIGINV * dy * dy);
    }
}

__global__ void __launch_bounds__(256) transpose_kernel(const float* __restrict__ feat) {
    __shared__ float tile[32][33];
    int b = blockIdx.z, n0 = blockIdx.x * 32, e0 = blockIdx.y * 32;
    int tx = threadIdx.x & 31, ty = threadIdx.x >> 5;
    const float* src = feat + ((size_t)b * 4096 + n0) * 256 + e0;
#pragma unroll
    for (int j = 0; j < 4; j++)
        tile[ty + j * 8][tx] = src[(size_t)(ty + j * 8) * 256 + tx];
    __syncthreads();
    float* dst = &g_ft[b][e0][n0];
#pragma unroll
    for (int j = 0; j < 4; j++)
        dst[(size_t)(ty + j * 8) * 4096 + tx] =
            __uint_as_float(f2tf32(tile[tx][ty + j * 8]));
}

// ---------------- main mma.sync tf32 kernel ----------------
// 256 blocks: blk = b*64 + mt*2 + et. Block tile: 128p x 128e (e-half et).
// D = W[128 x 4096] * Ft^T, K chunks of 32. 8 warps, warp tile 32p x 64e.
// smem/stage: ws[128][36] (18432) + fs[128][36] (18432) = 36864, x2 buffers
// -> 73728 B per CTA -> 2 CTAs/SM, all 256 blocks resident in one wave.
#define WSB   18432
#define STAGE 36864
#define SMEMT (2 * STAGE)   // 73728

__global__ void __launch_bounds__(256, 2) mma_kernel(float* __restrict__ out) {
    extern __shared__ char smem[];
    uint32_t sb = smem_u32(smem);
    const int t = threadIdx.x, w = t >> 5, l = t & 31;
    const int blk = blockIdx.x, b = blk >> 6, mt = (blk >> 1) & 31, et = blk & 1;

    // --- staging maps: 2 threads per row, 16 k-values each ---
    const int sr = t >> 1, kseg = (t & 1) * 16;
    const float* exrow = &g_ex[b][mt * 2 + (sr >> 6)][0];
    const float* eyrow = &g_ey[b][sr & 63][0];
    const uint32_t wsAddr = sb + sr * 144 + kseg * 4;
    const float* ftrow = &g_ft[b][et * 128 + (t >> 1)][0] + (t & 1) * 16;
    const uint32_t fsAddr = sb + WSB + (t >> 1) * 144 + (t & 1) * 64;

    // --- mma fragment maps: wm 0..3 (32p), wn 0..1 (64e) ---
    const int wm = w & 3, wn = w >> 2, g = l >> 2, tig = l & 3;
    const uint32_t aBase = sb + (wm * 32 + g) * 144 + tig * 4;
    const uint32_t bBase = sb + WSB + (wn * 64 + g) * 144 + tig * 4;

    float acc[2][8][4];
#pragma unroll
    for (int i = 0; i < 2; i++)
#pragma unroll
        for (int j = 0; j < 8; j++)
#pragma unroll
            for (int q = 0; q < 4; q++) acc[i][j][q] = 0.0f;
    float psum = 0.0f;

#define STAGE_CHUNK(c, s)                                                     \
    do {                                                                      \
        const uint32_t so = (s) * STAGE;                                      \
        const int nc = (c) * 32;                                              \
        const float* fsrc = ftrow + nc;                                       \
        _Pragma("unroll")                                                     \
        for (int j = 0; j < 4; j++)                                           \
            asm volatile("cp.async.cg.shared.global [%0], [%1], 16;"          \
                         :: "r"(fsAddr + so + 16 * j), "l"(fsrc + 4 * j)      \
                         : "memory");                                         \
        asm volatile("cp.async.commit_group;" ::: "memory");                  \
        _Pragma("unroll")                                                     \
        for (int q = 0; q < 4; q++) {                                         \
            float4 ex = *(const float4*)(exrow + nc + kseg + 4 * q);          \
            float4 ey = *(const float4*)(eyrow + nc + kseg + 4 * q);          \
            float p0 = ex.x * ey.x, p1 = ex.y * ey.y;                         \
            float p2 = ex.z * ey.z, p3 = ex.w * ey.w;                         \
            psum += (p0 + p1) + (p2 + p3);                                    \
            uint32_t w0 = f2tf32(p0), w1 = f2tf32(p1);                        \
            uint32_t w2 = f2tf32(p2), w3 = f2tf32(p3);                        \
            asm volatile("st.shared.v4.b32 [%0], {%1,%2,%3,%4};"              \
                         :: "r"(wsAddr + so + 16 * q),                        \
                            "r"(w0), "r"(w1), "r"(w2), "r"(w3) : "memory");   \
        }                                                                     \
    } while (0)

    STAGE_CHUNK(0, 0);

    for (int c = 0; c < 128; c++) {
        const int s = c & 1;
        if (c < 127) {
            STAGE_CHUNK(c + 1, s ^ 1);
            asm volatile("cp.async.wait_group 1;" ::: "memory");
        } else {
            asm volatile("cp.async.wait_group 0;" ::: "memory");
        }
        __syncthreads();

        const uint32_t so = s * STAGE;
#pragma unroll
        for (int kt = 0; kt < 4; kt++) {
            uint32_t a[2][4];
#pragma unroll
            for (int i = 0; i < 2; i++) {
                uint32_t ad = aBase + so + i * 2304 + kt * 32;
                a[i][0] = lds32(ad);
                a[i][1] = lds32(ad + 1152);
                a[i][2] = lds32(ad + 16);
                a[i][3] = lds32(ad + 1152 + 16);
            }
#pragma unroll
            for (int jn = 0; jn < 8; jn++) {
                uint32_t bd = bBase + so + jn * 1152 + kt * 32;
                uint32_t b0 = lds32(bd), b1 = lds32(bd + 16);
#pragma unroll
                for (int i = 0; i < 2; i++) {
                    float* d = acc[i][jn];
                    asm volatile(
                        "mma.sync.aligned.m16n8k8.row.col.f32.tf32.tf32.f32 "
                        "{%0,%1,%2,%3}, {%4,%5,%6,%7}, {%8,%9}, {%0,%1,%2,%3};"
                        : "+f"(d[0]), "+f"(d[1]), "+f"(d[2]), "+f"(d[3])
                        : "r"(a[i][0]), "r"(a[i][1]), "r"(a[i][2]), "r"(a[i][3]),
                          "r"(b0), "r"(b1));
                }
            }
        }
        __syncthreads();
    }

    // --- exact fp32 row-sum reduction (2 partials per row) ---
    float* sm = (float*)smem;          // stage buffers are dead now
    sm[t] = psum;
    __syncthreads();
    if (t < 128) sm[256 + t] = sm[2 * t] + sm[2 * t + 1];
    __syncthreads();

    // --- epilogue: normalize, scatter to [b][e][gx][gy] ---
    const size_t obase = (size_t)b * 256 * 4096;
#pragma unroll
    for (int i = 0; i < 2; i++) {
        int lp = wm * 32 + i * 16 + g;
        int p0 = mt * 128 + lp, p1 = p0 + 8;
        float inv0 = 1.0f / (sm[256 + lp] + EPSs);
        float inv1 = 1.0f / (sm[256 + lp + 8] + EPSs);
#pragma unroll
        for (int jn = 0; jn < 8; jn++) {
            int e0 = et * 128 + wn * 64 + jn * 8 + tig * 2;
            float* o0 = out + obase + (size_t)e0 * 4096;
            float* o1 = o0 + 4096;
            o0[p0] = acc[i][jn][0] * inv0;
            o1[p0] = acc[i][jn][1] * inv0;
            o0[p1] = acc[i][jn][2] * inv1;
            o1[p1] = acc[i][jn][3] * inv1;
        }
    }
}

extern "C" void kernel_launch(void* const* d_in, const int* in_sizes, int n_in,
                              void* d_out, int out_size) {
    const float* feat = (const float*)d_in[0];  // [4,4096,256]
    const float* pos  = (const float*)d_in[1];  // [4,4096,2]
    float* out = (float*)d_out;                 // [4,256,64,64]

    cudaFuncSetAttribute(mma_kernel,
                         cudaFuncAttributeMaxDynamicSharedMemorySize, SMEMT);

    table_kernel<<<256, 256>>>(pos);
    transpose_kernel<<<dim3(128, 8, 4), 256>>>(feat);
    mma_kernel<<<256, 256, SMEMT>>>(out);
}

// round 8
// speedup vs baseline: 2.1998x; 1.5661x over previous
#include <cuda_runtime.h>
#include <cuda_fp16.h>
#include <cstdint>

#define SIGINV 50.0f     // 1 / (2 * 0.1^2)
#define EPSs   1e-8f

// Separable RBF tables (fp32), fp16 transposed features
__device__ float  g_ex[4][64][4096];
__device__ float  g_ey[4][64][4096];
__device__ __half g_fth[4][256][4096];   // Fth[b][e][n] = half(F[b][n][e])

// ---------------- helpers ----------------
__device__ __forceinline__ uint32_t smem_u32(const void* p) {
    uint32_t a;
    asm("{ .reg .u64 t; cvta.to.shared.u64 t, %1; cvt.u32.u64 %0, t; }"
        : "=r"(a) : "l"(p));
    return a;
}
__device__ __forceinline__ uint32_t f16x2(float hi, float lo) {
    uint32_t r;
    asm("cvt.rn.f16x2.f32 %0, %1, %2;" : "=r"(r) : "f"(hi), "f"(lo));
    return r;
}
__device__ __forceinline__ uint32_t lds32(uint32_t a) {
    uint32_t v;
    asm volatile("ld.shared.b32 %0, [%1];" : "=r"(v) : "r"(a));
    return v;
}

// ---------------- pre-kernels ----------------
__global__ void __launch_bounds__(256) table_kernel(const float* __restrict__ pos) {
    int b = blockIdx.x >> 6, gi = blockIdx.x & 63;
    float gc = (float)gi * (1.0f / 63.0f);
    int t = threadIdx.x;
    const float2* p2 = (const float2*)pos + (size_t)b * 4096;
#pragma unroll
    for (int j = 0; j < 16; j++) {
        int n = t + j * 256;
        float2 p = p2[n];
        float dx = gc - p.x, dy = gc - p.y;
        g_ex[b][gi][n] = __expf(-SIGINV * dx * dx);
        g_ey[b][gi][n] = __expf(-SIGINV * dy * dy);
    }
}

__global__ void __launch_bounds__(256) transpose_kernel(const float* __restrict__ feat) {
    __shared__ float tile[32][33];
    int b = blockIdx.z, n0 = blockIdx.x * 32, e0 = blockIdx.y * 32;
    int tx = threadIdx.x & 31, ty = threadIdx.x >> 5;
    const float* src = feat + ((size_t)b * 4096 + n0) * 256 + e0;
#pragma unroll
    for (int j = 0; j < 4; j++)
        tile[ty + j * 8][tx] = src[(size_t)(ty + j * 8) * 256 + tx];
    __syncthreads();
    __half* dst = &g_fth[b][e0][n0];
#pragma unroll
    for (int j = 0; j < 4; j++)
        dst[(size_t)(ty + j * 8) * 4096 + tx] = __float2half_rn(tile[tx][ty + j * 8]);
}

// ---------------- main mma.sync fp16 kernel ----------------
// 256 blocks: blk = b*64 + mt*2 + et. Block tile: 128p x 128e.
// D = W[128 x 4096] * Fth^T, K chunks of 32 (2x m16n8k16 k-steps).
// 8 warps, warp tile 32p x 64e.
// smem/stage: A 128x80B + B 128x80B = 20480 B, double-buffered = 40960 B.
#define PITCH 80
#define ASIZE (128 * PITCH)     // 10240
#define STAGE (2 * ASIZE)       // 20480
#define SMEMT (2 * STAGE)       // 40960

__global__ void __launch_bounds__(256, 2) mma_kernel(float* __restrict__ out) {
    extern __shared__ char smem[];
    uint32_t sb = smem_u32(smem);
    const int t = threadIdx.x, w = t >> 5, l = t & 31;
    const int blk = blockIdx.x, b = blk >> 6, mt = (blk >> 1) & 31, et = blk & 1;

    // --- staging maps: 2 threads per row, 16 k-values (32 B) each ---
    const int sr = t >> 1, h = t & 1;
    const float* exrow = &g_ex[b][mt * 2 + (sr >> 6)][0];
    const float* eyrow = &g_ey[b][sr & 63][0];
    const uint32_t wsAddr = sb + sr * PITCH + h * 32;
    const __half* ftrow = &g_fth[b][et * 128 + sr][0] + h * 16;
    const uint32_t fsAddr = sb + ASIZE + sr * PITCH + h * 32;

    // --- mma fragment maps: wm 0..3 (32p), wn 0..1 (64e) ---
    const int wm = w & 3, wn = w >> 2, g = l >> 2, tig = l & 3;
    const uint32_t aBase = sb + (wm * 32 + g) * PITCH + tig * 4;
    const uint32_t bBase = sb + ASIZE + (wn * 64 + g) * PITCH + tig * 4;

    float acc[2][8][4];
#pragma unroll
    for (int i = 0; i < 2; i++)
#pragma unroll
        for (int j = 0; j < 8; j++)
#pragma unroll
            for (int q = 0; q < 4; q++) acc[i][j][q] = 0.0f;
    float psum = 0.0f;

#define STAGE_CHUNK(c, s)                                                     \
    do {                                                                      \
        const uint32_t so = (s) * STAGE;                                      \
        const int nc = (c) * 32;                                              \
        const __half* fsrc = ftrow + nc;                                      \
        asm volatile("cp.async.cg.shared.global [%0], [%1], 16;"              \
                     :: "r"(fsAddr + so), "l"(fsrc) : "memory");              \
        asm volatile("cp.async.cg.shared.global [%0], [%1], 16;"              \
                     :: "r"(fsAddr + so + 16), "l"(fsrc + 8) : "memory");     \
        asm volatile("cp.async.commit_group;" ::: "memory");                  \
        uint32_t wp[8];                                                       \
        _Pragma("unroll")                                                     \
        for (int q = 0; q < 4; q++) {                                         \
            float4 ex = *(const float4*)(exrow + nc + h * 16 + 4 * q);        \
            float4 ey = *(const float4*)(eyrow + nc + h * 16 + 4 * q);        \
            float p0 = ex.x * ey.x, p1 = ex.y * ey.y;                         \
            float p2 = ex.z * ey.z, p3 = ex.w * ey.w;                         \
            psum += (p0 + p1) + (p2 + p3);                                    \
            wp[2 * q]     = f16x2(p1, p0);                                    \
            wp[2 * q + 1] = f16x2(p3, p2);                                    \
        }                                                                     \
        asm volatile("st.shared.v4.b32 [%0], {%1,%2,%3,%4};"                  \
                     :: "r"(wsAddr + so), "r"(wp[0]), "r"(wp[1]),             \
                        "r"(wp[2]), "r"(wp[3]) : "memory");                   \
        asm volatile("st.shared.v4.b32 [%0], {%1,%2,%3,%4};"                  \
                     :: "r"(wsAddr + so + 16), "r"(wp[4]), "r"(wp[5]),        \
                        "r"(wp[6]), "r"(wp[7]) : "memory");                   \
    } while (0)

    STAGE_CHUNK(0, 0);

    for (int c = 0; c < 128; c++) {
        const int s = c & 1;
        if (c < 127) {
            STAGE_CHUNK(c + 1, s ^ 1);
            asm volatile("cp.async.wait_group 1;" ::: "memory");
        } else {
            asm volatile("cp.async.wait_group 0;" ::: "memory");
        }
        __syncthreads();

        const uint32_t so = s * STAGE;
#pragma unroll
        for (int kt = 0; kt < 2; kt++) {
            uint32_t a[2][4];
#pragma unroll
            for (int i = 0; i < 2; i++) {
                uint32_t ad = aBase + so + kt * 32 + i * 16 * PITCH;
                a[i][0] = lds32(ad);
                a[i][1] = lds32(ad + 8 * PITCH);
                a[i][2] = lds32(ad + 16);
                a[i][3] = lds32(ad + 8 * PITCH + 16);
            }
#pragma unroll
            for (int jn = 0; jn < 8; jn++) {
                uint32_t bd = bBase + so + kt * 32 + jn * 8 * PITCH;
                uint32_t b0 = lds32(bd), b1 = lds32(bd + 16);
#pragma unroll
                for (int i = 0; i < 2; i++) {
                    float* d = acc[i][jn];
                    asm volatile(
                        "mma.sync.aligned.m16n8k16.row.col.f32.f16.f16.f32 "
                        "{%0,%1,%2,%3}, {%4,%5,%6,%7}, {%8,%9}, {%0,%1,%2,%3};"
                        : "+f"(d[0]), "+f"(d[1]), "+f"(d[2]), "+f"(d[3])
                        : "r"(a[i][0]), "r"(a[i][1]), "r"(a[i][2]), "r"(a[i][3]),
                          "r"(b0), "r"(b1));
                }
            }
        }
        __syncthreads();
    }

    // --- exact fp32 row-sum reduction (2 partials per row) ---
    float* sm = (float*)smem;          // stage buffers are dead now
    sm[t] = psum;
    __syncthreads();
    if (t < 128) sm[256 + t] = sm[2 * t] + sm[2 * t + 1];
    __syncthreads();

    // --- epilogue: normalize, scatter to [b][e][gx][gy] ---
    const size_t obase = (size_t)b * 256 * 4096;
#pragma unroll
    for (int i = 0; i < 2; i++) {
        int lp = wm * 32 + i * 16 + g;
        int p0 = mt * 128 + lp, p1 = p0 + 8;
        float inv0 = 1.0f / (sm[256 + lp] + EPSs);
        float inv1 = 1.0f / (sm[256 + lp + 8] + EPSs);
#pragma unroll
        for (int jn = 0; jn < 8; jn++) {
            int e0 = et * 128 + wn * 64 + jn * 8 + tig * 2;
            float* o0 = out + obase + (size_t)e0 * 4096;
            float* o1 = o0 + 4096;
            o0[p0] = acc[i][jn][0] * inv0;
            o1[p0] = acc[i][jn][1] * inv0;
            o0[p1] = acc[i][jn][2] * inv1;
            o1[p1] = acc[i][jn][3] * inv1;
        }
    }
}

extern "C" void kernel_launch(void* const* d_in, const int* in_sizes, int n_in,
                              void* d_out, int out_size) {
    const float* feat = (const float*)d_in[0];  // [4,4096,256]
    const float* pos  = (const float*)d_in[1];  // [4,4096,2]
    float* out = (float*)d_out;                 // [4,256,64,64]

    cudaFuncSetAttribute(mma_kernel,
                         cudaFuncAttributeMaxDynamicSharedMemorySize, SMEMT);

    table_kernel<<<256, 256>>>(pos);
    transpose_kernel<<<dim3(128, 8, 4), 256>>>(feat);
    mma_kernel<<<256, 256, SMEMT>>>(out);
}